// round 12
// baseline (speedup 1.0000x reference)
#include <cuda_runtime.h>

#define NMAX 100000

// Aggregation buffer agg[dst] = sum_e w_e * x_src[src_e]; 25.6 MB static.
static __device__ __align__(16) float g_agg[NMAX * 64];

// ---------------------------------------------------------------------------
// tf32 / cp.async helpers
// ---------------------------------------------------------------------------
__device__ __forceinline__ unsigned f2tf32(float x) {
    unsigned u;
    asm("cvt.rna.tf32.f32 %0, %1;" : "=r"(u) : "f"(x));
    return u;
}

#define MMA_TF32(c0, c1, c2, c3, a0, a1, a2, a3, b0, b1)                     \
    asm volatile(                                                            \
        "mma.sync.aligned.m16n8k8.row.col.f32.tf32.tf32.f32 "               \
        "{%0,%1,%2,%3}, {%4,%5,%6,%7}, {%8,%9}, {%0,%1,%2,%3};"             \
        : "+f"(c0), "+f"(c1), "+f"(c2), "+f"(c3)                             \
        : "r"(a0), "r"(a1), "r"(a2), "r"(a3), "r"(b0), "r"(b1))

#define CP_ASYNC_16(smem_u32, gptr, szreg)                                   \
    asm volatile("cp.async.ca.shared.global [%0], [%1], 16, %2;"             \
                 :: "r"(smem_u32), "l"(gptr), "r"(szreg))
#define CP_ASYNC_COMMIT()  asm volatile("cp.async.commit_group;")
#define CP_ASYNC_WAIT0()   asm volatile("cp.async.wait_group 0;")

// Shared-tile geometry for the K=64 single-half GEMMs.
#define AS_STRIDE 68
#define BS_STRIDE 68
#define AS_FLOATS (128 * AS_STRIDE)
#define BS_FLOATS (64 * BS_STRIDE)
#define GEMM_SMEM_BYTES ((AS_FLOATS + BS_FLOATS) * 4)   // 52224 B

// ---------------------------------------------------------------------------
// Single-half tf32 GEMM body: acc (+)= A[rowbase..][0..64) @ W^T.
// Block 256 thr (8 warps), tile 128 rows x 64 cols, warp w: rows 16w..16w+15.
// A staged raw f32 via cp.async; tf32 cvt at consume. Bank-clean:
// stride 68 -> row g offset 4g banks; frag loads hit 4g+tg = 32 distinct.
// acc layout: acc[nt][0..3] = rows (g, g+8) x cols (nt*8+2tg, +1).
// ---------------------------------------------------------------------------
__device__ __forceinline__ void gemm_half_body(
    float* As, float* Bs, const float* __restrict__ A, const float* __restrict__ W,
    int rowbase, int N, int wr, int g, int tg, int tid, float acc[8][4])
{
    const unsigned as_base = (unsigned)__cvta_generic_to_shared(As);

    // cp.async A tile (128 x 64 f32)
    #pragma unroll
    for (int i = 0; i < 8; i++) {
        int f  = tid + i * 256;
        int r  = f >> 4;
        int k4 = f & 15;
        int gr = rowbase + r;
        bool ok = gr < N;
        const float* src = A + (size_t)(ok ? gr : 0) * 64 + k4 * 4;
        unsigned dst = as_base + (unsigned)(r * AS_STRIDE + k4 * 4) * 4u;
        int sz = ok ? 16 : 0;
        CP_ASYNC_16(dst, src, sz);
    }
    CP_ASYNC_COMMIT();

    // stage W (64x64) with tf32 cvt while A flies
    #pragma unroll
    for (int i = 0; i < 4; i++) {
        int f  = tid + i * 256;
        int c  = f >> 4;
        int k4 = f & 15;
        float4 v = *(const float4*)(W + c * 64 + k4 * 4);
        float* b = Bs + c * BS_STRIDE + k4 * 4;
        b[0] = __uint_as_float(f2tf32(v.x));
        b[1] = __uint_as_float(f2tf32(v.y));
        b[2] = __uint_as_float(f2tf32(v.z));
        b[3] = __uint_as_float(f2tf32(v.w));
    }

    CP_ASYNC_WAIT0();
    __syncthreads();

    #pragma unroll
    for (int kc = 0; kc < 8; kc++) {
        const int k0 = kc * 8;
        const float* arow0 = As + (wr + g) * AS_STRIDE + k0;
        const float* arow1 = arow0 + 8 * AS_STRIDE;
        unsigned a0 = f2tf32(arow0[tg]);
        unsigned a1 = f2tf32(arow1[tg]);
        unsigned a2 = f2tf32(arow0[tg + 4]);
        unsigned a3 = f2tf32(arow1[tg + 4]);
        #pragma unroll
        for (int nt = 0; nt < 8; nt++) {
            const float* brow = Bs + (nt * 8 + g) * BS_STRIDE + k0;
            unsigned b0 = __float_as_uint(brow[tg]);
            unsigned b1 = __float_as_uint(brow[tg + 4]);
            MMA_TF32(acc[nt][0], acc[nt][1], acc[nt][2], acc[nt][3],
                     a0, a1, a2, a3, b0, b1);
        }
    }
}

// ---------------------------------------------------------------------------
// Combined kernel: interleaved scatter blocks + self-GEMM blocks.
// Every 13th block (bid % 13 == 12, g < NG) is a GEMM tile; the rest scatter.
// Scatter: g_agg[dst] += x_src[src]*w (8 edges/thread, 16 lanes/edge, v4 RED).
// GEMM:    out[tile] = x_dst @ W_self^T + b.
// ---------------------------------------------------------------------------
__global__ void __launch_bounds__(256) combined_kernel(
    const float* __restrict__ xsrc,
    const void* __restrict__ ei_raw, const float* __restrict__ ew,
    int E, int n_src,
    const float* __restrict__ Xd, const float* __restrict__ Wself,
    const float* __restrict__ bias, float* __restrict__ out, int N, int NG)
{
    extern __shared__ __align__(16) float smem[];
    const int bid = blockIdx.x;
    const int gq  = bid / 13;
    const bool is_gemm = ((bid % 13) == 12) && (gq < NG);

    if (is_gemm) {
        // ---------------- self-GEMM tile ----------------
        float* As = smem;
        float* Bs = smem + AS_FLOATS;
        const int tid  = threadIdx.x;
        const int lane = tid & 31;
        const int wid  = tid >> 5;
        const int g    = lane >> 2;
        const int tg   = lane & 3;
        const int wr   = wid * 16;
        const int rowbase = gq * 128;

        float acc[8][4];
        #pragma unroll
        for (int nt = 0; nt < 8; nt++) {
            float b0 = bias[nt * 8 + 2 * tg];
            float b1 = bias[nt * 8 + 2 * tg + 1];
            acc[nt][0] = b0; acc[nt][1] = b1;
            acc[nt][2] = b0; acc[nt][3] = b1;
        }

        gemm_half_body(As, Bs, Xd, Wself, rowbase, N, wr, g, tg, tid, acc);

        const int r0 = rowbase + wr + g;
        const int r1 = r0 + 8;
        if (r0 < N) {
            float* yrow = out + (size_t)r0 * 64;
            #pragma unroll
            for (int nt = 0; nt < 8; nt++)
                *(float2*)(yrow + nt * 8 + 2 * tg) =
                    make_float2(acc[nt][0], acc[nt][1]);
        }
        if (r1 < N) {
            float* yrow = out + (size_t)r1 * 64;
            #pragma unroll
            for (int nt = 0; nt < 8; nt++)
                *(float2*)(yrow + nt * 8 + 2 * tg) =
                    make_float2(acc[nt][2], acc[nt][3]);
        }
        return;
    }

    // ---------------- scatter block ----------------
    // dtype detect (JAX demotes int64->int32 when x64 off): warp 0 samples
    // 32 int64 slots (in-bounds under both layouts); int32 pairs have random
    // high words -> out of [0, n_src).
    __shared__ int sflag;
    {
        const long long* ei = (const long long*)ei_raw;
        if (threadIdx.x < 32) {
            long long stride = (E > 32) ? (E / 32) : 1;
            long long idx = (long long)threadIdx.x * stride;
            if (idx > E - 1) idx = E - 1;
            long long v = ei[idx];
            bool bad = (v < 0 || v >= n_src);
            unsigned m = __ballot_sync(0xffffffffu, bad);
            if (threadIdx.x == 0) sflag = (m == 0) ? 1 : 0;
        }
        __syncthreads();
    }
    const int is64 = sflag;

    const int sid = bid - min(NG, (bid + 1) / 13);   // scatter block index
    const long long t = (long long)sid * 256 + threadIdx.x;
    const int lane = (int)(t & 15);
    const long long e0 = (t >> 4) * 8;
    if (e0 >= E) return;
    const int n = (E - e0 >= 8) ? 8 : (int)(E - e0);

    int s[8], d[8];
    float w[8];
    if (is64) {
        const long long* ei = (const long long*)ei_raw;
        #pragma unroll
        for (int i = 0; i < 8; i++) if (i < n) {
            s[i] = (int)ei[e0 + i];
            d[i] = (int)ei[(long long)E + e0 + i];
        }
    } else {
        const int* ei = (const int*)ei_raw;
        #pragma unroll
        for (int i = 0; i < 8; i++) if (i < n) {
            s[i] = ei[e0 + i];
            d[i] = ei[(long long)E + e0 + i];
        }
    }
    #pragma unroll
    for (int i = 0; i < 8; i++) if (i < n) w[i] = ew[e0 + i];

    float4 v[8];
    #pragma unroll
    for (int i = 0; i < 8; i++) if (i < n)
        v[i] = *(const float4*)(xsrc + (size_t)s[i] * 64 + lane * 4);

    #pragma unroll
    for (int i = 0; i < 8; i++) if (i < n) {
        const float wi = w[i];
        float4 vv = v[i];
        vv.x *= wi; vv.y *= wi; vv.z *= wi; vv.w *= wi;
        float* dst = g_agg + (size_t)d[i] * 64 + lane * 4;
        asm volatile("red.global.add.v4.f32 [%0], {%1, %2, %3, %4};"
                     :: "l"(dst), "f"(vv.x), "f"(vv.y), "f"(vv.z), "f"(vv.w)
                     : "memory");
    }
}

// ---------------------------------------------------------------------------
// Epilogue: out += g_agg @ W_nei^T   (tf32, K=64 single half)
// ---------------------------------------------------------------------------
__global__ void __launch_bounds__(256) nei_gemm_kernel(
    const float* __restrict__ Wnei, float* __restrict__ out, int N)
{
    extern __shared__ __align__(16) float smem[];
    float* As = smem;
    float* Bs = smem + AS_FLOATS;

    const int tid  = threadIdx.x;
    const int lane = tid & 31;
    const int wid  = tid >> 5;
    const int g    = lane >> 2;
    const int tg   = lane & 3;
    const int wr   = wid * 16;
    const int rowbase = blockIdx.x * 128;

    float acc[8][4];
    #pragma unroll
    for (int nt = 0; nt < 8; nt++)
        acc[nt][0] = acc[nt][1] = acc[nt][2] = acc[nt][3] = 0.f;

    gemm_half_body(As, Bs, g_agg, Wnei, rowbase, N, wr, g, tg, tid, acc);

    const int r0 = rowbase + wr + g;
    const int r1 = r0 + 8;
    if (r0 < N) {
        float* yrow = out + (size_t)r0 * 64;
        #pragma unroll
        for (int nt = 0; nt < 8; nt++) {
            float2 yv = *(float2*)(yrow + nt * 8 + 2 * tg);
            yv.x += acc[nt][0]; yv.y += acc[nt][1];
            *(float2*)(yrow + nt * 8 + 2 * tg) = yv;
        }
    }
    if (r1 < N) {
        float* yrow = out + (size_t)r1 * 64;
        #pragma unroll
        for (int nt = 0; nt < 8; nt++) {
            float2 yv = *(float2*)(yrow + nt * 8 + 2 * tg);
            yv.x += acc[nt][2]; yv.y += acc[nt][3];
            *(float2*)(yrow + nt * 8 + 2 * tg) = yv;
        }
    }
}

// ---------------------------------------------------------------------------
// Inputs: 0:x_src f32[Ns*64] 1:x_dst f32[Nd*64] 2:edge_index[2E] (i32/i64)
//         3:edge_weight f32[E] 4:W_nei [64,64] 5:W_self [64,64] 6:b_self [64]
// Output: f32 [Nd*64]
// ---------------------------------------------------------------------------
extern "C" void kernel_launch(void* const* d_in, const int* in_sizes, int n_in,
                              void* d_out, int out_size)
{
    const float* x_src  = (const float*)d_in[0];
    const float* x_dst  = (const float*)d_in[1];
    const void*  ei     = d_in[2];
    const float* ew     = (const float*)d_in[3];
    const float* W_nei  = (const float*)d_in[4];
    const float* W_self = (const float*)d_in[5];
    const float* b_self = (const float*)d_in[6];
    float*       out    = (float*)d_out;

    const int n_src = in_sizes[0] / 64;
    const int n_dst = in_sizes[1] / 64;
    const int E     = in_sizes[3];

    float* aggp = nullptr;
    cudaGetSymbolAddress((void**)&aggp, g_agg);

    static int smem_set = 0;
    if (!smem_set) {
        cudaFuncSetAttribute(combined_kernel,
                             cudaFuncAttributeMaxDynamicSharedMemorySize,
                             GEMM_SMEM_BYTES);
        cudaFuncSetAttribute(nei_gemm_kernel,
                             cudaFuncAttributeMaxDynamicSharedMemorySize,
                             GEMM_SMEM_BYTES);
        smem_set = 1;
    }

    // 0) zero agg
    cudaMemsetAsync(aggp, 0, (size_t)n_dst * 64 * sizeof(float));

    // 1) combined: scatter (agg) + self-GEMM (out), interleaved blocks
    {
        long long groups  = ((long long)E + 7) / 8;
        long long sthreads = groups * 16;
        int ns = (int)((sthreads + 255) / 256);        // scatter blocks
        int ng = (n_dst + 127) / 128;                  // gemm tiles
        combined_kernel<<<ns + ng, 256, GEMM_SMEM_BYTES>>>(
            x_src, ei, ew, E, n_src, x_dst, W_self, b_self, out, n_dst, ng);
    }

    // 2) epilogue: out += agg @ W_nei^T
    nei_gemm_kernel<<<(n_dst + 127) / 128, 256, GEMM_SMEM_BYTES>>>(
        W_nei, out, n_dst);
}

// round 13
// speedup vs baseline: 1.1102x; 1.1102x over previous
#include <cuda_runtime.h>

#define NMAX 100000

// Aggregation buffer agg[dst] = sum_e w_e * x_src[src_e]; 25.6 MB static.
static __device__ __align__(16) float g_agg[NMAX * 64];

// ---------------------------------------------------------------------------
// Edge scatter (input space): g_agg[dst] += x_src[src] * w.
// Proven 90.6us structure — folded dtype detect, 8 edges/thread, v4 REDs.
// At the REDG lane-rate floor. NO dynamic smem (full occupancy).
// ---------------------------------------------------------------------------
__global__ void __launch_bounds__(256) scatter_kernel(
    const float* __restrict__ xsrc,
    const void* __restrict__ ei_raw,    // [2, E]: src row then dst row
    const float* __restrict__ ew,       // [E]
    int E, int n_src)
{
    // dtype detect (JAX demotes int64->int32 when x64 off): warp 0 samples
    // 32 int64 slots (in-bounds under both layouts); int32 pairs have random
    // high words -> out of [0, n_src).
    __shared__ int sflag;
    {
        const long long* ei = (const long long*)ei_raw;
        if (threadIdx.x < 32) {
            long long stride = (E > 32) ? (E / 32) : 1;
            long long idx = (long long)threadIdx.x * stride;
            if (idx > E - 1) idx = E - 1;
            long long v = ei[idx];
            bool bad = (v < 0 || v >= n_src);
            unsigned m = __ballot_sync(0xffffffffu, bad);
            if (threadIdx.x == 0) sflag = (m == 0) ? 1 : 0;
        }
        __syncthreads();
    }
    const int is64 = sflag;

    const long long t = (long long)blockIdx.x * blockDim.x + threadIdx.x;
    const int lane = (int)(t & 15);
    const long long e0 = (t >> 4) * 8;
    if (e0 >= E) return;
    const int n = (E - e0 >= 8) ? 8 : (int)(E - e0);

    int s[8], d[8];
    float w[8];
    if (is64) {
        const long long* ei = (const long long*)ei_raw;
        #pragma unroll
        for (int i = 0; i < 8; i++) if (i < n) {
            s[i] = (int)ei[e0 + i];
            d[i] = (int)ei[(long long)E + e0 + i];
        }
    } else {
        const int* ei = (const int*)ei_raw;
        #pragma unroll
        for (int i = 0; i < 8; i++) if (i < n) {
            s[i] = ei[e0 + i];
            d[i] = ei[(long long)E + e0 + i];
        }
    }
    #pragma unroll
    for (int i = 0; i < 8; i++) if (i < n) w[i] = ew[e0 + i];

    float4 v[8];
    #pragma unroll
    for (int i = 0; i < 8; i++) if (i < n)
        v[i] = *(const float4*)(xsrc + (size_t)s[i] * 64 + lane * 4);

    #pragma unroll
    for (int i = 0; i < 8; i++) if (i < n) {
        const float wi = w[i];
        float4 vv = v[i];
        vv.x *= wi; vv.y *= wi; vv.z *= wi; vv.w *= wi;
        float* dst = g_agg + (size_t)d[i] * 64 + lane * 4;
        asm volatile("red.global.add.v4.f32 [%0], {%1, %2, %3, %4};"
                     :: "l"(dst), "f"(vv.x), "f"(vv.y), "f"(vv.z), "f"(vv.w)
                     : "memory");
    }
}

// ---------------------------------------------------------------------------
// tf32 / cp.async helpers
// ---------------------------------------------------------------------------
__device__ __forceinline__ unsigned f2tf32(float x) {
    unsigned u;
    asm("cvt.rna.tf32.f32 %0, %1;" : "=r"(u) : "f"(x));
    return u;
}

#define MMA_TF32(c0, c1, c2, c3, a0, a1, a2, a3, b0, b1)                     \
    asm volatile(                                                            \
        "mma.sync.aligned.m16n8k8.row.col.f32.tf32.tf32.f32 "               \
        "{%0,%1,%2,%3}, {%4,%5,%6,%7}, {%8,%9}, {%0,%1,%2,%3};"             \
        : "+f"(c0), "+f"(c1), "+f"(c2), "+f"(c3)                             \
        : "r"(a0), "r"(a1), "r"(a2), "r"(a3), "r"(b0), "r"(b1))

#define CP_ASYNC_16(smem_u32, gptr, szreg)                                   \
    asm volatile("cp.async.ca.shared.global [%0], [%1], 16, %2;"             \
                 :: "r"(smem_u32), "l"(gptr), "r"(szreg))
#define CP_ASYNC_COMMIT()  asm volatile("cp.async.commit_group;")
#define CP_ASYNC_WAIT(n)   asm volatile("cp.async.wait_group %0;" :: "n"(n))

#define AS_STRIDE 68
#define BS_STRIDE 132
#define AS_FLOATS (128 * AS_STRIDE)
#define BS_FLOATS (64 * BS_STRIDE)
#define GEMM_SMEM_BYTES ((2 * AS_FLOATS + BS_FLOATS) * 4)   // 103424 B

// ---------------------------------------------------------------------------
// Persistent fused tf32 GEMM: out = x_dst @ W_self^T + g_agg @ W_nei^T + b.
// Grid = 2 CTAs/SM exactly (no wave quantization). Each CTA stages B once,
// then streams its tiles as chunks (tile, half): half0 = x_dst row-tile,
// half1 = agg row-tile. Double-buffered cp.async across chunks: chunk c+2
// is issued right after the MMA on chunk c -> steady state hides all load
// latency. acc init with bias at half0; stored after half1.
// ---------------------------------------------------------------------------
__global__ void __launch_bounds__(256, 2) persistent_gemm_kernel(
    const float* __restrict__ Xd, const float* __restrict__ Wself,
    const float* __restrict__ Wnei, const float* __restrict__ bias,
    float* __restrict__ out, int N, int ntiles, int G)
{
    extern __shared__ __align__(16) float smem[];
    float* As0 = smem;
    float* As1 = smem + AS_FLOATS;
    float* Bs  = smem + 2 * AS_FLOATS;

    const int tid  = threadIdx.x;
    const int lane = tid & 31;
    const int wid  = tid >> 5;
    const int g    = lane >> 2;
    const int tg   = lane & 3;
    const int wr   = wid * 16;
    const int bid  = blockIdx.x;

    if (bid >= ntiles) return;
    const int nt_cta  = (ntiles - 1 - bid) / G + 1;
    const int nchunks = 2 * nt_cta;

    const unsigned as_base[2] = {
        (unsigned)__cvta_generic_to_shared(As0),
        (unsigned)__cvta_generic_to_shared(As1)
    };
    const float* aggp = g_agg;

    // Per-thread staging coords (8 float4 slots covering 128x64).
    int srow[8], sk4[8];
    #pragma unroll
    for (int i = 0; i < 8; i++) {
        int f = tid + i * 256;
        srow[i] = f >> 4;
        sk4[i]  = f & 15;
    }

    // chunk c -> tile bid + (c>>1)*G, half c&1, buffer c&1... careful:
    // buffer index is (c & 1) XOR'd with nothing; chunks alternate buffers.
    #define ISSUE_CHUNK(c)                                                    \
    do {                                                                      \
        const int _tile = bid + ((c) >> 1) * G;                               \
        const int _rb   = _tile * 128;                                        \
        const float* _A = ((c) & 1) ? aggp : Xd;                              \
        const unsigned _base = as_base[(c) & 1];                              \
        _Pragma("unroll")                                                     \
        for (int _i = 0; _i < 8; _i++) {                                      \
            int _gr = _rb + srow[_i];                                         \
            bool _ok = _gr < N;                                               \
            const float* _src = _A + (size_t)(_ok ? _gr : 0) * 64 + sk4[_i] * 4; \
            unsigned _dst = _base + (unsigned)(srow[_i] * AS_STRIDE + sk4[_i] * 4) * 4u; \
            int _sz = _ok ? 16 : 0;                                           \
            CP_ASYNC_16(_dst, _src, _sz);                                     \
        }                                                                     \
        CP_ASYNC_COMMIT();                                                    \
    } while (0)

    // Prologue: two chunks in flight before anything else.
    ISSUE_CHUNK(0);
    if (nchunks > 1) ISSUE_CHUNK(1);

    // Stage B (both halves) once, tf32 cvt, while A flies.
    #pragma unroll
    for (int m = 0; m < 2; m++) {
        const float* Wm = m ? Wnei : Wself;
        #pragma unroll
        for (int i = 0; i < 4; i++) {
            int f  = tid + i * 256;
            int c  = f >> 4;
            int k4 = f & 15;
            float4 v = *(const float4*)(Wm + c * 64 + k4 * 4);
            float* b = Bs + c * BS_STRIDE + m * 64 + k4 * 4;
            b[0] = __uint_as_float(f2tf32(v.x));
            b[1] = __uint_as_float(f2tf32(v.y));
            b[2] = __uint_as_float(f2tf32(v.z));
            b[3] = __uint_as_float(f2tf32(v.w));
        }
    }

    // Bias fragments (col bias shared by both acc rows).
    float bp0[8], bp1[8];
    #pragma unroll
    for (int nt = 0; nt < 8; nt++) {
        bp0[nt] = bias[nt * 8 + 2 * tg];
        bp1[nt] = bias[nt * 8 + 2 * tg + 1];
    }

    float acc[8][4];

    #pragma unroll 1
    for (int c = 0; c < nchunks; c++) {
        const int h = c & 1;
        if (h == 0) {
            #pragma unroll
            for (int nt = 0; nt < 8; nt++) {
                acc[nt][0] = bp0[nt]; acc[nt][1] = bp1[nt];
                acc[nt][2] = bp0[nt]; acc[nt][3] = bp1[nt];
            }
        }

        if (c == nchunks - 1) { CP_ASYNC_WAIT(0); } else { CP_ASYNC_WAIT(1); }
        __syncthreads();

        const float* As = h ? As1 : As0;
        #pragma unroll
        for (int kc = 0; kc < 8; kc++) {
            const int k0 = kc * 8;
            const float* arow0 = As + (wr + g) * AS_STRIDE + k0;
            const float* arow1 = arow0 + 8 * AS_STRIDE;
            unsigned a0 = f2tf32(arow0[tg]);
            unsigned a1 = f2tf32(arow1[tg]);
            unsigned a2 = f2tf32(arow0[tg + 4]);
            unsigned a3 = f2tf32(arow1[tg + 4]);
            #pragma unroll
            for (int nt = 0; nt < 8; nt++) {
                const float* brow = Bs + (nt * 8 + g) * BS_STRIDE + h * 64 + k0;
                unsigned b0 = __float_as_uint(brow[tg]);
                unsigned b1 = __float_as_uint(brow[tg + 4]);
                MMA_TF32(acc[nt][0], acc[nt][1], acc[nt][2], acc[nt][3],
                         a0, a1, a2, a3, b0, b1);
            }
        }

        __syncthreads();                 // all warps done reading this buffer
        if (c + 2 < nchunks) ISSUE_CHUNK(c + 2);   // refill early

        if (h == 1) {
            const int rowbase = (bid + (c >> 1) * G) * 128;
            const int r0 = rowbase + wr + g;
            const int r1 = r0 + 8;
            if (r0 < N) {
                float* yrow = out + (size_t)r0 * 64;
                #pragma unroll
                for (int nt = 0; nt < 8; nt++)
                    *(float2*)(yrow + nt * 8 + 2 * tg) =
                        make_float2(acc[nt][0], acc[nt][1]);
            }
            if (r1 < N) {
                float* yrow = out + (size_t)r1 * 64;
                #pragma unroll
                for (int nt = 0; nt < 8; nt++)
                    *(float2*)(yrow + nt * 8 + 2 * tg) =
                        make_float2(acc[nt][2], acc[nt][3]);
            }
        }
    }
    #undef ISSUE_CHUNK
}

// ---------------------------------------------------------------------------
// Inputs: 0:x_src f32[Ns*64] 1:x_dst f32[Nd*64] 2:edge_index[2E] (i32/i64)
//         3:edge_weight f32[E] 4:W_nei [64,64] 5:W_self [64,64] 6:b_self [64]
// Output: f32 [Nd*64]
// ---------------------------------------------------------------------------
extern "C" void kernel_launch(void* const* d_in, const int* in_sizes, int n_in,
                              void* d_out, int out_size)
{
    const float* x_src  = (const float*)d_in[0];
    const float* x_dst  = (const float*)d_in[1];
    const void*  ei     = d_in[2];
    const float* ew     = (const float*)d_in[3];
    const float* W_nei  = (const float*)d_in[4];
    const float* W_self = (const float*)d_in[5];
    const float* b_self = (const float*)d_in[6];
    float*       out    = (float*)d_out;

    const int n_src = in_sizes[0] / 64;
    const int n_dst = in_sizes[1] / 64;
    const int E     = in_sizes[3];

    float* aggp = nullptr;
    cudaGetSymbolAddress((void**)&aggp, g_agg);

    static int smem_set = 0;
    if (!smem_set) {
        cudaFuncSetAttribute(persistent_gemm_kernel,
                             cudaFuncAttributeMaxDynamicSharedMemorySize,
                             GEMM_SMEM_BYTES);
        smem_set = 1;
    }

    // 0) zero agg
    cudaMemsetAsync(aggp, 0, (size_t)n_dst * 64 * sizeof(float));

    // 1) scatter in input space (8 edges per thread, 16 lanes/edge)
    {
        long long groups  = ((long long)E + 7) / 8;
        long long threads = groups * 16;
        int blocks = (int)((threads + 255) / 256);
        scatter_kernel<<<blocks, 256>>>(x_src, ei, ew, E, n_src);
    }

    // 2) persistent fused tf32 GEMM (2 CTAs/SM, tiles streamed per CTA)
    {
        int ntiles = (n_dst + 127) / 128;
        int G = ntiles < 296 ? ntiles : 296;
        persistent_gemm_kernel<<<G, 256, GEMM_SMEM_BYTES>>>(
            x_dst, W_self, W_nei, b_self, out, n_dst, ntiles, G);
    }
}